// round 6
// baseline (speedup 1.0000x reference)
#include <cuda_runtime.h>
#include <cuda_fp16.h>
#include <mma.h>

using namespace nvcuda;

#define NWIN 8192
#define KW 32
#define CDIM 192
#define NH 6
#define HID 768
#define POS_BND 25
#define RPE_NUM 51
#define SCALE 0.17677669529663687f
#define FULLM 0xffffffffu

// padded smem strides (elements); byte stride mod 128 != 0 to avoid LDSM conflicts
#define XLD   200   // x / attn-out rows (half)
#define QLD   584   // qkv rows (half)
#define BLD   104   // 96-col weight slice rows (half), 208 B
#define W1LD  136
#define HBLD  136
#define W2LD  200
#define ALD   36    // attn logits rows (float), 144 B
#define PLD   40    // attn probs rows (half), 80 B
#define SGLD  20    // stage rows (float), 80 B

// ----- cp.async helpers -----
__device__ __forceinline__ void cp16(void* dst_smem, const void* src_gmem) {
    unsigned d = (unsigned)__cvta_generic_to_shared(dst_smem);
    asm volatile("cp.async.cg.shared.global [%0], [%1], 16;\n" :: "r"(d), "l"(src_gmem));
}
__device__ __forceinline__ void cp_commit() { asm volatile("cp.async.commit_group;\n"); }
__device__ __forceinline__ void cp_wait0()  { asm volatile("cp.async.wait_group 0;\n"); }

// ---------------- device scratch ----------------
__device__ __half g_qkv_wh[CDIM * 3 * CDIM];
__device__ __half g_proj_wh[CDIM * CDIM];
__device__ __half g_w1h[CDIM * HID];
__device__ __half g_w2h[HID * CDIM];
__device__ float  g_data2[(size_t)NWIN * KW * CDIM];

__global__ void convert_weights(const float* __restrict__ qkv_w,
                                const float* __restrict__ proj_w,
                                const float* __restrict__ w1,
                                const float* __restrict__ w2) {
    int stride = gridDim.x * blockDim.x;
    int t0 = blockIdx.x * blockDim.x + threadIdx.x;
    for (int i = t0; i < CDIM * 3 * CDIM; i += stride) g_qkv_wh[i]  = __float2half(qkv_w[i]);
    for (int i = t0; i < CDIM * CDIM;     i += stride) g_proj_wh[i] = __float2half(proj_w[i]);
    for (int i = t0; i < CDIM * HID;      i += stride) g_w1h[i]     = __float2half(w1[i]);
    for (int i = t0; i < HID * CDIM;      i += stride) g_w2h[i]     = __float2half(w2[i]);
}

// ================= Kernel A: 1 window (32 tokens) per CTA, 256 threads, 2 CTAs/SM =================
struct __align__(16) SmemA {
    __half xh[32 * XLD];                    // 12800 B
    __half qkvh[32 * QLD];                  // 37376 B
    union {
        __half bs[CDIM * BLD];              // 39936 B (96-col weight slice)
        struct {
            float  attn[NH * KW * ALD];     // 27648 B
            __half attnP[NH * KW * PLD];    // 15360 B
        } a;                                // 43008 B
    } u;
    float stage[8 * 16 * SGLD];             // 10240 B
    float rpe_t[153 * NH];
    float qkv_b[3 * CDIM];
    float proj_b[CDIM];
    float ln_g[CDIM];
    float ln_b[CDIM];
};

__global__ __launch_bounds__(256, 2) void kernelA(
    const float* __restrict__ data, const float* __restrict__ mask,
    const int* __restrict__ rel_pos, const float* __restrict__ ln1_g,
    const float* __restrict__ ln1_b, const float* __restrict__ qkv_b,
    const float* __restrict__ rpe_table, const float* __restrict__ proj_b)
{
    extern __shared__ char smem_raw[];
    SmemA& s = *reinterpret_cast<SmemA*>(smem_raw);
    const int tid  = threadIdx.x;
    const int warp = tid >> 5, lane = tid & 31;
    const long long tok0 = (long long)blockIdx.x * KW;

    // ---- front-batched rel_pos/mask prefetch into registers ----
    int pr0[4], pr1[4], pr2[4];
    float pm[4];
    #pragma unroll
    for (int pi = 0; pi < 4; pi++) {
        int r = warp + pi * 8;
        long long base = (tok0 + r) * KW + lane;
        const int* rp = rel_pos + base * 3;
        pr0[pi] = rp[0]; pr1[pi] = rp[1]; pr2[pi] = rp[2];
        pm[pi]  = mask[base];
    }

    // ---- params ----
    for (int i = tid; i < 3 * CDIM; i += 256) s.qkv_b[i] = qkv_b[i];
    for (int i = tid; i < CDIM; i += 256) {
        s.proj_b[i] = proj_b[i];
        s.ln_g[i]   = ln1_g[i];
        s.ln_b[i]   = ln1_b[i];
    }
    for (int i = tid; i < 153 * NH; i += 256) s.rpe_t[i] = rpe_table[i];

    // ---- issue QKV weight slice 0 (overlaps LN1) ----
    for (int i = tid; i < CDIM * 12; i += 256) {
        int k = i / 12, c8 = (i % 12) << 3;
        cp16(&s.u.bs[k * BLD + c8], &g_qkv_wh[k * 576 + c8]);
    }
    cp_commit();
    __syncthreads();   // params visible for LN1

    // ---- LN1 (4 rows per warp) ----
    for (int r = warp; r < KW; r += 8) {
        const float* dp = data + (tok0 + r) * CDIM;
        float v[6], su = 0.f, sq = 0.f;
        #pragma unroll
        for (int j = 0; j < 6; j++) { v[j] = dp[lane + 32 * j]; su += v[j]; sq += v[j] * v[j]; }
        #pragma unroll
        for (int o = 16; o > 0; o >>= 1) {
            su += __shfl_xor_sync(FULLM, su, o);
            sq += __shfl_xor_sync(FULLM, sq, o);
        }
        float mean = su * (1.0f / CDIM);
        float rstd = rsqrtf(sq * (1.0f / CDIM) - mean * mean + 1e-5f);
        #pragma unroll
        for (int j = 0; j < 6; j++) {
            int c = lane + 32 * j;
            s.xh[r * XLD + c] = __float2half((v[j] - mean) * rstd * s.ln_g[c] + s.ln_b[c]);
        }
    }
    cp_wait0();
    __syncthreads();   // xh + slice0 ready

    // ---- QKV GEMM: 6 slices of 96 cols ----
    for (int sl = 0; sl < 6; sl++) {
        int cb = sl * 96;
        for (int j = warp; j < 12; j += 8) {
            int rt = j & 1, ct = j >> 1;
            wmma::fragment<wmma::accumulator, 16, 16, 16, float> cf;
            wmma::fill_fragment(cf, 0.0f);
            for (int k = 0; k < CDIM; k += 16) {
                wmma::fragment<wmma::matrix_a, 16, 16, 16, __half, wmma::row_major> af;
                wmma::fragment<wmma::matrix_b, 16, 16, 16, __half, wmma::row_major> bf;
                wmma::load_matrix_sync(af, &s.xh[(rt * 16) * XLD + k], XLD);
                wmma::load_matrix_sync(bf, &s.u.bs[k * BLD + ct * 16], BLD);
                wmma::mma_sync(cf, af, bf, cf);
            }
            wmma::store_matrix_sync(&s.stage[warp * 16 * SGLD], cf, SGLD, wmma::mem_row_major);
            __syncwarp();
            #pragma unroll
            for (int q = 0; q < 8; q++) {
                int idx = q * 32 + lane;
                int rr = idx >> 4, cc = idx & 15;
                int g = cb + ct * 16 + cc;
                float val = s.stage[warp * 16 * SGLD + rr * SGLD + cc] + s.qkv_b[g];
                if (cb < CDIM) val *= SCALE;    // slices 0,1 are Q
                s.qkvh[(rt * 16 + rr) * QLD + g] = __float2half(val);
            }
            __syncwarp();
        }
        __syncthreads();            // all warps done with bs
        if (sl < 5) {
            int cbn = (sl + 1) * 96;
            for (int i = tid; i < CDIM * 12; i += 256) {
                int k = i / 12, c8 = (i % 12) << 3;
                cp16(&s.u.bs[k * BLD + c8], &g_qkv_wh[k * 576 + cbn + c8]);
            }
            cp_commit();
            cp_wait0();
        }
        __syncthreads();
    }
    // bs region now free -> attn union usable

    // ---- logits Q@K^T: 24 tile jobs ----
    for (int j = warp; j < 24; j += 8) {
        int h = j >> 2, q = j & 3, mi = q >> 1, ni = q & 1;
        const __half* qp = &s.qkvh[h * 32];
        const __half* kp = &s.qkvh[CDIM + h * 32];
        wmma::fragment<wmma::accumulator, 16, 16, 16, float> cf;
        wmma::fill_fragment(cf, 0.0f);
        #pragma unroll
        for (int kk = 0; kk < 2; kk++) {
            wmma::fragment<wmma::matrix_a, 16, 16, 16, __half, wmma::row_major> af;
            wmma::fragment<wmma::matrix_b, 16, 16, 16, __half, wmma::col_major> bf;
            wmma::load_matrix_sync(af, qp + (mi * 16) * QLD + kk * 16, QLD);
            wmma::load_matrix_sync(bf, kp + (ni * 16) * QLD + kk * 16, QLD);
            wmma::mma_sync(cf, af, bf, cf);
        }
        wmma::store_matrix_sync(&s.u.a.attn[(h * 32 + mi * 16) * ALD + ni * 16],
                                cf, ALD, wmma::mem_row_major);
    }
    __syncthreads();

    // ---- RPE + mask + softmax (prefetched regs) ----
    #pragma unroll
    for (int pi = 0; pi < 4; pi++) {
        int r = warp + pi * 8;
        int a0 = min(POS_BND, max(-POS_BND, pr0[pi])) + POS_BND;
        int a1 = min(POS_BND, max(-POS_BND, pr1[pi])) + POS_BND + RPE_NUM;
        int a2 = min(POS_BND, max(-POS_BND, pr2[pi])) + POS_BND + 2 * RPE_NUM;
        float m = pm[pi];
        #pragma unroll
        for (int h = 0; h < NH; h++) {
            float add = s.rpe_t[a0 * NH + h] + s.rpe_t[a1 * NH + h] + s.rpe_t[a2 * NH + h] + m;
            float val = s.u.a.attn[(h * 32 + r) * ALD + lane] + add;
            float mx = val;
            #pragma unroll
            for (int o = 16; o > 0; o >>= 1) mx = fmaxf(mx, __shfl_xor_sync(FULLM, mx, o));
            float e = __expf(val - mx);
            float su = e;
            #pragma unroll
            for (int o = 16; o > 0; o >>= 1) su += __shfl_xor_sync(FULLM, su, o);
            s.u.a.attnP[(h * 32 + r) * PLD + lane] = __float2half(e / su);
        }
    }
    __syncthreads();

    // ---- P@V -> xh ----
    for (int j = warp; j < 24; j += 8) {
        int h = j >> 2, q = j & 3, mi = q >> 1, ni = q & 1;
        const __half* pp = &s.u.a.attnP[h * 32 * PLD];
        const __half* vp = &s.qkvh[2 * CDIM + h * 32];
        wmma::fragment<wmma::accumulator, 16, 16, 16, float> cf;
        wmma::fill_fragment(cf, 0.0f);
        #pragma unroll
        for (int kk = 0; kk < 2; kk++) {
            wmma::fragment<wmma::matrix_a, 16, 16, 16, __half, wmma::row_major> af;
            wmma::fragment<wmma::matrix_b, 16, 16, 16, __half, wmma::row_major> bf;
            wmma::load_matrix_sync(af, pp + (mi * 16) * PLD + kk * 16, PLD);
            wmma::load_matrix_sync(bf, vp + (kk * 16) * QLD + ni * 16, QLD);
            wmma::mma_sync(cf, af, bf, cf);
        }
        wmma::store_matrix_sync(&s.stage[warp * 16 * SGLD], cf, SGLD, wmma::mem_row_major);
        __syncwarp();
        #pragma unroll
        for (int q2 = 0; q2 < 8; q2++) {
            int idx = q2 * 32 + lane;
            int rr = idx >> 4, cc = idx & 15;
            s.xh[(mi * 16 + rr) * XLD + h * 32 + ni * 16 + cc] =
                __float2half(s.stage[warp * 16 * SGLD + rr * SGLD + cc]);
        }
        __syncwarp();
    }
    __syncthreads();   // xh ready; attnP no longer needed -> bs reusable

    // ---- proj + residual: 2 slices of 96 cols ----
    for (int ps = 0; ps < 2; ps++) {
        int cb = ps * 96;
        for (int i = tid; i < CDIM * 12; i += 256) {
            int k = i / 12, c8 = (i % 12) << 3;
            cp16(&s.u.bs[k * BLD + c8], &g_proj_wh[k * CDIM + cb + c8]);
        }
        cp_commit();
        cp_wait0();
        __syncthreads();
        for (int j = warp; j < 12; j += 8) {
            int rt = j & 1, ct = j >> 1;
            wmma::fragment<wmma::accumulator, 16, 16, 16, float> cf;
            wmma::fill_fragment(cf, 0.0f);
            for (int k = 0; k < CDIM; k += 16) {
                wmma::fragment<wmma::matrix_a, 16, 16, 16, __half, wmma::row_major> af;
                wmma::fragment<wmma::matrix_b, 16, 16, 16, __half, wmma::row_major> bf;
                wmma::load_matrix_sync(af, &s.xh[(rt * 16) * XLD + k], XLD);
                wmma::load_matrix_sync(bf, &s.u.bs[k * BLD + ct * 16], BLD);
                wmma::mma_sync(cf, af, bf, cf);
            }
            wmma::store_matrix_sync(&s.stage[warp * 16 * SGLD], cf, SGLD, wmma::mem_row_major);
            __syncwarp();
            #pragma unroll
            for (int q = 0; q < 8; q++) {
                int idx = q * 32 + lane;
                int rr = idx >> 4, cc = idx & 15;
                int g = cb + ct * 16 + cc;
                long long gi = (tok0 + rt * 16 + rr) * CDIM + g;
                g_data2[gi] = s.stage[warp * 16 * SGLD + rr * SGLD + cc] + s.proj_b[g] + data[gi];
            }
            __syncwarp();
        }
        __syncthreads();
    }
}

// ================= Kernel B: 128 rows/CTA, 512 threads, cp.async pipelined =================
struct __align__(16) SmemB {
    __half yh[128 * XLD];
    __half w1s[CDIM * W1LD];
    __half w2s[128 * W2LD];
    __half hb[128 * HBLD];
    float  stage[16 * 16 * SGLD];
    float  ln_g[CDIM];
    float  ln_b[CDIM];
    float  b1[HID];
    float  b2[CDIM];
};

__global__ __launch_bounds__(512, 1) void kernelB(
    const float* __restrict__ ln2_g, const float* __restrict__ ln2_b,
    const float* __restrict__ b1, const float* __restrict__ b2,
    float* __restrict__ out)
{
    extern __shared__ char smem_raw[];
    SmemB& s = *reinterpret_cast<SmemB*>(smem_raw);
    const int tid  = threadIdx.x;
    const int warp = tid >> 5, lane = tid & 31;
    const long long row0 = (long long)blockIdx.x * 128;
    const int rt = warp & 7, cg = warp >> 3;

    for (int i = tid; i < CDIM; i += 512) {
        s.ln_g[i] = ln2_g[i];
        s.ln_b[i] = ln2_b[i];
        s.b2[i]   = b2[i];
    }
    for (int i = tid; i < HID; i += 512) s.b1[i] = b1[i];

    // issue w1s[0] load (overlaps LN2)
    for (int i = tid; i < CDIM * 16; i += 512) {
        int k = i >> 4, c8 = (i & 15) << 3;
        cp16(&s.w1s[k * W1LD + c8], &g_w1h[k * HID + c8]);
    }
    cp_commit();
    __syncthreads();   // params visible

    // LN2
    for (int r = warp; r < 128; r += 16) {
        const float* dp = g_data2 + (row0 + r) * CDIM;
        float v[6], su = 0.f, sq = 0.f;
        #pragma unroll
        for (int j = 0; j < 6; j++) { v[j] = dp[lane + 32 * j]; su += v[j]; sq += v[j] * v[j]; }
        #pragma unroll
        for (int o = 16; o > 0; o >>= 1) {
            su += __shfl_xor_sync(FULLM, su, o);
            sq += __shfl_xor_sync(FULLM, sq, o);
        }
        float mean = su * (1.0f / CDIM);
        float rstd = rsqrtf(sq * (1.0f / CDIM) - mean * mean + 1e-5f);
        #pragma unroll
        for (int j = 0; j < 6; j++) {
            int c = lane + 32 * j;
            s.yh[r * XLD + c] = __float2half((v[j] - mean) * rstd * s.ln_g[c] + s.ln_b[c]);
        }
    }
    cp_wait0();
    __syncthreads();   // yh + w1s[0] ready

    wmma::fragment<wmma::accumulator, 16, 16, 16, float> acc[6];
    #pragma unroll
    for (int c = 0; c < 6; c++) wmma::fill_fragment(acc[c], 0.0f);

    for (int it = 0; it < 6; it++) {
        int hb0 = it * 128;

        // issue w2s[it] load (overlaps gemm1)
        for (int i = tid; i < 128 * 24; i += 512) {
            int r = i / 24, c8 = (i % 24) << 3;
            cp16(&s.w2s[r * W2LD + c8], &g_w2h[(hb0 + r) * CDIM + c8]);
        }
        cp_commit();

        // gemm1: hb = gelu(yh @ w1s + b1)
        {
            wmma::fragment<wmma::accumulator, 16, 16, 16, float> cf[4];
            #pragma unroll
            for (int c = 0; c < 4; c++) wmma::fill_fragment(cf[c], 0.0f);
            for (int k = 0; k < CDIM; k += 16) {
                wmma::fragment<wmma::matrix_a, 16, 16, 16, __half, wmma::row_major> af;
                wmma::load_matrix_sync(af, &s.yh[(rt * 16) * XLD + k], XLD);
                #pragma unroll
                for (int c = 0; c < 4; c++) {
                    wmma::fragment<wmma::matrix_b, 16, 16, 16, __half, wmma::row_major> bf;
                    wmma::load_matrix_sync(bf, &s.w1s[k * W1LD + (cg * 4 + c) * 16], W1LD);
                    wmma::mma_sync(cf[c], af, bf, cf[c]);
                }
            }
            #pragma unroll
            for (int c = 0; c < 4; c++) {
                wmma::store_matrix_sync(&s.stage[warp * 16 * SGLD], cf[c], SGLD, wmma::mem_row_major);
                __syncwarp();
                #pragma unroll
                for (int q = 0; q < 8; q++) {
                    int idx = q * 32 + lane;
                    int rr = idx >> 4, cc = idx & 15;
                    float v = s.stage[warp * 16 * SGLD + rr * SGLD + cc]
                              + s.b1[hb0 + (cg * 4 + c) * 16 + cc];
                    v = 0.5f * v * (1.0f + erff(v * 0.70710678118654752f));
                    s.hb[(rt * 16 + rr) * HBLD + (cg * 4 + c) * 16 + cc] = __float2half(v);
                }
                __syncwarp();
            }
        }
        cp_wait0();
        __syncthreads();   // w2s arrived, hb visible

        // issue w1s[it+1] load (overlaps gemm2)
        if (it < 5) {
            int hbn = hb0 + 128;
            for (int i = tid; i < CDIM * 16; i += 512) {
                int k = i >> 4, c8 = (i & 15) << 3;
                cp16(&s.w1s[k * W1LD + c8], &g_w1h[k * HID + hbn + c8]);
            }
            cp_commit();
        }

        // gemm2: acc += hb @ w2s
        for (int kk = 0; kk < 128; kk += 16) {
            wmma::fragment<wmma::matrix_a, 16, 16, 16, __half, wmma::row_major> af;
            wmma::load_matrix_sync(af, &s.hb[(rt * 16) * HBLD + kk], HBLD);
            #pragma unroll
            for (int c = 0; c < 6; c++) {
                wmma::fragment<wmma::matrix_b, 16, 16, 16, __half, wmma::row_major> bf;
                wmma::load_matrix_sync(bf, &s.w2s[kk * W2LD + cg * 96 + c * 16], W2LD);
                wmma::mma_sync(acc[c], af, bf, acc[c]);
            }
        }
        cp_wait0();
        __syncthreads();   // w1s[it+1] ready; safe to overwrite hb/w2s next iter
    }

    // epilogue
    #pragma unroll
    for (int c = 0; c < 6; c++) {
        wmma::store_matrix_sync(&s.stage[warp * 16 * SGLD], acc[c], SGLD, wmma::mem_row_major);
        __syncwarp();
        #pragma unroll
        for (int q = 0; q < 8; q++) {
            int idx = q * 32 + lane;
            int rr = idx >> 4, cc = idx & 15;
            int col = cg * 96 + c * 16 + cc;
            long long gi = (row0 + rt * 16 + rr) * CDIM + col;
            out[gi] = s.stage[warp * 16 * SGLD + rr * SGLD + cc] + s.b2[col] + g_data2[gi];
        }
        __syncwarp();
    }
}

// ---------------- launch ----------------
extern "C" void kernel_launch(void* const* d_in, const int* in_sizes, int n_in,
                              void* d_out, int out_size) {
    const float* data      = (const float*)d_in[0];
    const float* mask      = (const float*)d_in[1];
    const int*   rel_pos   = (const int*)  d_in[2];
    const float* ln1_g     = (const float*)d_in[3];
    const float* ln1_b     = (const float*)d_in[4];
    const float* qkv_w     = (const float*)d_in[5];
    const float* qkv_b     = (const float*)d_in[6];
    const float* rpe_table = (const float*)d_in[7];
    const float* proj_w    = (const float*)d_in[8];
    const float* proj_b    = (const float*)d_in[9];
    const float* ln2_g     = (const float*)d_in[10];
    const float* ln2_b     = (const float*)d_in[11];
    const float* mlp_w1    = (const float*)d_in[12];
    const float* mlp_b1    = (const float*)d_in[13];
    const float* mlp_w2    = (const float*)d_in[14];
    const float* mlp_b2    = (const float*)d_in[15];
    float* out = (float*)d_out;

    cudaFuncSetAttribute(kernelA, cudaFuncAttributeMaxDynamicSharedMemorySize, (int)sizeof(SmemA));
    cudaFuncSetAttribute(kernelB, cudaFuncAttributeMaxDynamicSharedMemorySize, (int)sizeof(SmemB));

    convert_weights<<<576, 256>>>(qkv_w, proj_w, mlp_w1, mlp_w2);
    kernelA<<<NWIN, 256, sizeof(SmemA)>>>(data, mask, rel_pos, ln1_g, ln1_b,
                                          qkv_b, rpe_table, proj_b);
    kernelB<<<(NWIN * KW) / 128, 512, sizeof(SmemB)>>>(ln2_g, ln2_b, mlp_b1, mlp_b2, out);
}

// round 7
// speedup vs baseline: 1.0008x; 1.0008x over previous
#include <cuda_runtime.h>
#include <cuda_fp16.h>
#include <mma.h>

using namespace nvcuda;

#define NWIN 8192
#define KW 32
#define CDIM 192
#define NH 6
#define HID 768
#define POS_BND 25
#define RPE_NUM 51
#define SCALE 0.17677669529663687f
#define FULLM 0xffffffffu

// padded smem strides (elements); byte stride mod 128 != 0 to avoid LDSM conflicts
#define XLD   200   // x / attn-out rows (half)
#define QLD   584   // qkv rows (half)
#define BLD   104   // 96-col weight slice rows (half), 208 B
#define W1LD  136
#define HBLD  136
#define W2LD  200
#define ALD   36    // attn logits rows (float), 144 B
#define PLD   40    // attn probs rows (half), 80 B
#define SGLD  20    // stage rows (float), 80 B

// ----- cp.async helpers -----
__device__ __forceinline__ void cp16(void* dst_smem, const void* src_gmem) {
    unsigned d = (unsigned)__cvta_generic_to_shared(dst_smem);
    asm volatile("cp.async.cg.shared.global [%0], [%1], 16;\n" :: "r"(d), "l"(src_gmem));
}
__device__ __forceinline__ void cp_commit() { asm volatile("cp.async.commit_group;\n"); }
__device__ __forceinline__ void cp_wait0()  { asm volatile("cp.async.wait_group 0;\n"); }

// ---------------- device scratch ----------------
__device__ __half g_qkv_wh[CDIM * 3 * CDIM];
__device__ __half g_proj_wh[CDIM * CDIM];
__device__ __half g_w1h[CDIM * HID];
__device__ __half g_w2h[HID * CDIM];
__device__ float  g_data2[(size_t)NWIN * KW * CDIM];

__global__ void convert_weights(const float* __restrict__ qkv_w,
                                const float* __restrict__ proj_w,
                                const float* __restrict__ w1,
                                const float* __restrict__ w2) {
    int stride = gridDim.x * blockDim.x;
    int t0 = blockIdx.x * blockDim.x + threadIdx.x;
    for (int i = t0; i < CDIM * 3 * CDIM; i += stride) g_qkv_wh[i]  = __float2half(qkv_w[i]);
    for (int i = t0; i < CDIM * CDIM;     i += stride) g_proj_wh[i] = __float2half(proj_w[i]);
    for (int i = t0; i < CDIM * HID;      i += stride) g_w1h[i]     = __float2half(w1[i]);
    for (int i = t0; i < HID * CDIM;      i += stride) g_w2h[i]     = __float2half(w2[i]);
}

// ================= Kernel A: 1 window (32 tokens) per CTA, 256 threads, 2 CTAs/SM =================
struct __align__(16) SmemA {
    __half xh[32 * XLD];                    // 12800 B
    __half qkvh[32 * QLD];                  // 37376 B
    union {
        __half bs[CDIM * BLD];              // 39936 B (96-col weight slice)
        struct {
            float  attn[NH * KW * ALD];     // 27648 B
            __half attnP[NH * KW * PLD];    // 15360 B
        } a;                                // 43008 B
    } u;
    float stage[8 * 16 * SGLD];             // 10240 B
    float rpe_t[153 * NH];
    float qkv_b[3 * CDIM];
    float proj_b[CDIM];
    float ln_g[CDIM];
    float ln_b[CDIM];
};

__global__ __launch_bounds__(256, 2) void kernelA(
    const float* __restrict__ data, const float* __restrict__ mask,
    const int* __restrict__ rel_pos, const float* __restrict__ ln1_g,
    const float* __restrict__ ln1_b, const float* __restrict__ qkv_b,
    const float* __restrict__ rpe_table, const float* __restrict__ proj_b)
{
    extern __shared__ char smem_raw[];
    SmemA& s = *reinterpret_cast<SmemA*>(smem_raw);
    const int tid  = threadIdx.x;
    const int warp = tid >> 5, lane = tid & 31;
    const long long tok0 = (long long)blockIdx.x * KW;

    // ---- front-batched rel_pos/mask prefetch into registers ----
    int pr0[4], pr1[4], pr2[4];
    float pm[4];
    #pragma unroll
    for (int pi = 0; pi < 4; pi++) {
        int r = warp + pi * 8;
        long long base = (tok0 + r) * KW + lane;
        const int* rp = rel_pos + base * 3;
        pr0[pi] = rp[0]; pr1[pi] = rp[1]; pr2[pi] = rp[2];
        pm[pi]  = mask[base];
    }

    // ---- params ----
    for (int i = tid; i < 3 * CDIM; i += 256) s.qkv_b[i] = qkv_b[i];
    for (int i = tid; i < CDIM; i += 256) {
        s.proj_b[i] = proj_b[i];
        s.ln_g[i]   = ln1_g[i];
        s.ln_b[i]   = ln1_b[i];
    }
    for (int i = tid; i < 153 * NH; i += 256) s.rpe_t[i] = rpe_table[i];

    // ---- issue QKV weight slice 0 (overlaps LN1) ----
    for (int i = tid; i < CDIM * 12; i += 256) {
        int k = i / 12, c8 = (i % 12) << 3;
        cp16(&s.u.bs[k * BLD + c8], &g_qkv_wh[k * 576 + c8]);
    }
    cp_commit();
    __syncthreads();   // params visible for LN1

    // ---- LN1 (4 rows per warp) ----
    for (int r = warp; r < KW; r += 8) {
        const float* dp = data + (tok0 + r) * CDIM;
        float v[6], su = 0.f, sq = 0.f;
        #pragma unroll
        for (int j = 0; j < 6; j++) { v[j] = dp[lane + 32 * j]; su += v[j]; sq += v[j] * v[j]; }
        #pragma unroll
        for (int o = 16; o > 0; o >>= 1) {
            su += __shfl_xor_sync(FULLM, su, o);
            sq += __shfl_xor_sync(FULLM, sq, o);
        }
        float mean = su * (1.0f / CDIM);
        float rstd = rsqrtf(sq * (1.0f / CDIM) - mean * mean + 1e-5f);
        #pragma unroll
        for (int j = 0; j < 6; j++) {
            int c = lane + 32 * j;
            s.xh[r * XLD + c] = __float2half((v[j] - mean) * rstd * s.ln_g[c] + s.ln_b[c]);
        }
    }
    cp_wait0();
    __syncthreads();   // xh + slice0 ready

    // ---- QKV GEMM: 6 slices of 96 cols ----
    for (int sl = 0; sl < 6; sl++) {
        int cb = sl * 96;
        for (int j = warp; j < 12; j += 8) {
            int rt = j & 1, ct = j >> 1;
            wmma::fragment<wmma::accumulator, 16, 16, 16, float> cf;
            wmma::fill_fragment(cf, 0.0f);
            for (int k = 0; k < CDIM; k += 16) {
                wmma::fragment<wmma::matrix_a, 16, 16, 16, __half, wmma::row_major> af;
                wmma::fragment<wmma::matrix_b, 16, 16, 16, __half, wmma::row_major> bf;
                wmma::load_matrix_sync(af, &s.xh[(rt * 16) * XLD + k], XLD);
                wmma::load_matrix_sync(bf, &s.u.bs[k * BLD + ct * 16], BLD);
                wmma::mma_sync(cf, af, bf, cf);
            }
            wmma::store_matrix_sync(&s.stage[warp * 16 * SGLD], cf, SGLD, wmma::mem_row_major);
            __syncwarp();
            #pragma unroll
            for (int q = 0; q < 8; q++) {
                int idx = q * 32 + lane;
                int rr = idx >> 4, cc = idx & 15;
                int g = cb + ct * 16 + cc;
                float val = s.stage[warp * 16 * SGLD + rr * SGLD + cc] + s.qkv_b[g];
                if (cb < CDIM) val *= SCALE;    // slices 0,1 are Q
                s.qkvh[(rt * 16 + rr) * QLD + g] = __float2half(val);
            }
            __syncwarp();
        }
        __syncthreads();            // all warps done with bs
        if (sl < 5) {
            int cbn = (sl + 1) * 96;
            for (int i = tid; i < CDIM * 12; i += 256) {
                int k = i / 12, c8 = (i % 12) << 3;
                cp16(&s.u.bs[k * BLD + c8], &g_qkv_wh[k * 576 + cbn + c8]);
            }
            cp_commit();
            cp_wait0();
        }
        __syncthreads();
    }
    // bs region now free -> attn union usable

    // ---- logits Q@K^T: 24 tile jobs ----
    for (int j = warp; j < 24; j += 8) {
        int h = j >> 2, q = j & 3, mi = q >> 1, ni = q & 1;
        const __half* qp = &s.qkvh[h * 32];
        const __half* kp = &s.qkvh[CDIM + h * 32];
        wmma::fragment<wmma::accumulator, 16, 16, 16, float> cf;
        wmma::fill_fragment(cf, 0.0f);
        #pragma unroll
        for (int kk = 0; kk < 2; kk++) {
            wmma::fragment<wmma::matrix_a, 16, 16, 16, __half, wmma::row_major> af;
            wmma::fragment<wmma::matrix_b, 16, 16, 16, __half, wmma::col_major> bf;
            wmma::load_matrix_sync(af, qp + (mi * 16) * QLD + kk * 16, QLD);
            wmma::load_matrix_sync(bf, kp + (ni * 16) * QLD + kk * 16, QLD);
            wmma::mma_sync(cf, af, bf, cf);
        }
        wmma::store_matrix_sync(&s.u.a.attn[(h * 32 + mi * 16) * ALD + ni * 16],
                                cf, ALD, wmma::mem_row_major);
    }
    __syncthreads();

    // ---- RPE + mask + softmax (prefetched regs) ----
    #pragma unroll
    for (int pi = 0; pi < 4; pi++) {
        int r = warp + pi * 8;
        int a0 = min(POS_BND, max(-POS_BND, pr0[pi])) + POS_BND;
        int a1 = min(POS_BND, max(-POS_BND, pr1[pi])) + POS_BND + RPE_NUM;
        int a2 = min(POS_BND, max(-POS_BND, pr2[pi])) + POS_BND + 2 * RPE_NUM;
        float m = pm[pi];
        #pragma unroll
        for (int h = 0; h < NH; h++) {
            float add = s.rpe_t[a0 * NH + h] + s.rpe_t[a1 * NH + h] + s.rpe_t[a2 * NH + h] + m;
            float val = s.u.a.attn[(h * 32 + r) * ALD + lane] + add;
            float mx = val;
            #pragma unroll
            for (int o = 16; o > 0; o >>= 1) mx = fmaxf(mx, __shfl_xor_sync(FULLM, mx, o));
            float e = __expf(val - mx);
            float su = e;
            #pragma unroll
            for (int o = 16; o > 0; o >>= 1) su += __shfl_xor_sync(FULLM, su, o);
            s.u.a.attnP[(h * 32 + r) * PLD + lane] = __float2half(e / su);
        }
    }
    __syncthreads();

    // ---- P@V -> xh ----
    for (int j = warp; j < 24; j += 8) {
        int h = j >> 2, q = j & 3, mi = q >> 1, ni = q & 1;
        const __half* pp = &s.u.a.attnP[h * 32 * PLD];
        const __half* vp = &s.qkvh[2 * CDIM + h * 32];
        wmma::fragment<wmma::accumulator, 16, 16, 16, float> cf;
        wmma::fill_fragment(cf, 0.0f);
        #pragma unroll
        for (int kk = 0; kk < 2; kk++) {
            wmma::fragment<wmma::matrix_a, 16, 16, 16, __half, wmma::row_major> af;
            wmma::fragment<wmma::matrix_b, 16, 16, 16, __half, wmma::row_major> bf;
            wmma::load_matrix_sync(af, pp + (mi * 16) * PLD + kk * 16, PLD);
            wmma::load_matrix_sync(bf, vp + (kk * 16) * QLD + ni * 16, QLD);
            wmma::mma_sync(cf, af, bf, cf);
        }
        wmma::store_matrix_sync(&s.stage[warp * 16 * SGLD], cf, SGLD, wmma::mem_row_major);
        __syncwarp();
        #pragma unroll
        for (int q2 = 0; q2 < 8; q2++) {
            int idx = q2 * 32 + lane;
            int rr = idx >> 4, cc = idx & 15;
            s.xh[(mi * 16 + rr) * XLD + h * 32 + ni * 16 + cc] =
                __float2half(s.stage[warp * 16 * SGLD + rr * SGLD + cc]);
        }
        __syncwarp();
    }
    __syncthreads();   // xh ready; attnP no longer needed -> bs reusable

    // ---- proj + residual: 2 slices of 96 cols ----
    for (int ps = 0; ps < 2; ps++) {
        int cb = ps * 96;
        for (int i = tid; i < CDIM * 12; i += 256) {
            int k = i / 12, c8 = (i % 12) << 3;
            cp16(&s.u.bs[k * BLD + c8], &g_proj_wh[k * CDIM + cb + c8]);
        }
        cp_commit();
        cp_wait0();
        __syncthreads();
        for (int j = warp; j < 12; j += 8) {
            int rt = j & 1, ct = j >> 1;
            wmma::fragment<wmma::accumulator, 16, 16, 16, float> cf;
            wmma::fill_fragment(cf, 0.0f);
            for (int k = 0; k < CDIM; k += 16) {
                wmma::fragment<wmma::matrix_a, 16, 16, 16, __half, wmma::row_major> af;
                wmma::fragment<wmma::matrix_b, 16, 16, 16, __half, wmma::row_major> bf;
                wmma::load_matrix_sync(af, &s.xh[(rt * 16) * XLD + k], XLD);
                wmma::load_matrix_sync(bf, &s.u.bs[k * BLD + ct * 16], BLD);
                wmma::mma_sync(cf, af, bf, cf);
            }
            wmma::store_matrix_sync(&s.stage[warp * 16 * SGLD], cf, SGLD, wmma::mem_row_major);
            __syncwarp();
            #pragma unroll
            for (int q = 0; q < 8; q++) {
                int idx = q * 32 + lane;
                int rr = idx >> 4, cc = idx & 15;
                int g = cb + ct * 16 + cc;
                long long gi = (tok0 + rt * 16 + rr) * CDIM + g;
                g_data2[gi] = s.stage[warp * 16 * SGLD + rr * SGLD + cc] + s.proj_b[g] + data[gi];
            }
            __syncwarp();
        }
        __syncthreads();
    }
}

// ================= Kernel B: 128 rows/CTA, 512 threads, cp.async pipelined =================
struct __align__(16) SmemB {
    __half yh[128 * XLD];
    __half w1s[CDIM * W1LD];
    __half w2s[128 * W2LD];
    __half hb[128 * HBLD];
    float  stage[16 * 16 * SGLD];
    float  ln_g[CDIM];
    float  ln_b[CDIM];
    float  b1[HID];
    float  b2[CDIM];
};

__global__ __launch_bounds__(512, 1) void kernelB(
    const float* __restrict__ ln2_g, const float* __restrict__ ln2_b,
    const float* __restrict__ b1, const float* __restrict__ b2,
    float* __restrict__ out)
{
    extern __shared__ char smem_raw[];
    SmemB& s = *reinterpret_cast<SmemB*>(smem_raw);
    const int tid  = threadIdx.x;
    const int warp = tid >> 5, lane = tid & 31;
    const long long row0 = (long long)blockIdx.x * 128;
    const int rt = warp & 7, cg = warp >> 3;

    for (int i = tid; i < CDIM; i += 512) {
        s.ln_g[i] = ln2_g[i];
        s.ln_b[i] = ln2_b[i];
        s.b2[i]   = b2[i];
    }
    for (int i = tid; i < HID; i += 512) s.b1[i] = b1[i];

    // issue w1s[0] load (overlaps LN2)
    for (int i = tid; i < CDIM * 16; i += 512) {
        int k = i >> 4, c8 = (i & 15) << 3;
        cp16(&s.w1s[k * W1LD + c8], &g_w1h[k * HID + c8]);
    }
    cp_commit();
    __syncthreads();   // params visible

    // LN2
    for (int r = warp; r < 128; r += 16) {
        const float* dp = g_data2 + (row0 + r) * CDIM;
        float v[6], su = 0.f, sq = 0.f;
        #pragma unroll
        for (int j = 0; j < 6; j++) { v[j] = dp[lane + 32 * j]; su += v[j]; sq += v[j] * v[j]; }
        #pragma unroll
        for (int o = 16; o > 0; o >>= 1) {
            su += __shfl_xor_sync(FULLM, su, o);
            sq += __shfl_xor_sync(FULLM, sq, o);
        }
        float mean = su * (1.0f / CDIM);
        float rstd = rsqrtf(sq * (1.0f / CDIM) - mean * mean + 1e-5f);
        #pragma unroll
        for (int j = 0; j < 6; j++) {
            int c = lane + 32 * j;
            s.yh[r * XLD + c] = __float2half((v[j] - mean) * rstd * s.ln_g[c] + s.ln_b[c]);
        }
    }
    cp_wait0();
    __syncthreads();   // yh + w1s[0] ready

    wmma::fragment<wmma::accumulator, 16, 16, 16, float> acc[6];
    #pragma unroll
    for (int c = 0; c < 6; c++) wmma::fill_fragment(acc[c], 0.0f);

    for (int it = 0; it < 6; it++) {
        int hb0 = it * 128;

        // issue w2s[it] load (overlaps gemm1)
        for (int i = tid; i < 128 * 24; i += 512) {
            int r = i / 24, c8 = (i % 24) << 3;
            cp16(&s.w2s[r * W2LD + c8], &g_w2h[(hb0 + r) * CDIM + c8]);
        }
        cp_commit();

        // gemm1: hb = gelu(yh @ w1s + b1)
        {
            wmma::fragment<wmma::accumulator, 16, 16, 16, float> cf[4];
            #pragma unroll
            for (int c = 0; c < 4; c++) wmma::fill_fragment(cf[c], 0.0f);
            for (int k = 0; k < CDIM; k += 16) {
                wmma::fragment<wmma::matrix_a, 16, 16, 16, __half, wmma::row_major> af;
                wmma::load_matrix_sync(af, &s.yh[(rt * 16) * XLD + k], XLD);
                #pragma unroll
                for (int c = 0; c < 4; c++) {
                    wmma::fragment<wmma::matrix_b, 16, 16, 16, __half, wmma::row_major> bf;
                    wmma::load_matrix_sync(bf, &s.w1s[k * W1LD + (cg * 4 + c) * 16], W1LD);
                    wmma::mma_sync(cf[c], af, bf, cf[c]);
                }
            }
            #pragma unroll
            for (int c = 0; c < 4; c++) {
                wmma::store_matrix_sync(&s.stage[warp * 16 * SGLD], cf[c], SGLD, wmma::mem_row_major);
                __syncwarp();
                #pragma unroll
                for (int q = 0; q < 8; q++) {
                    int idx = q * 32 + lane;
                    int rr = idx >> 4, cc = idx & 15;
                    float v = s.stage[warp * 16 * SGLD + rr * SGLD + cc]
                              + s.b1[hb0 + (cg * 4 + c) * 16 + cc];
                    v = 0.5f * v * (1.0f + erff(v * 0.70710678118654752f));
                    s.hb[(rt * 16 + rr) * HBLD + (cg * 4 + c) * 16 + cc] = __float2half(v);
                }
                __syncwarp();
            }
        }
        cp_wait0();
        __syncthreads();   // w2s arrived, hb visible

        // issue w1s[it+1] load (overlaps gemm2)
        if (it < 5) {
            int hbn = hb0 + 128;
            for (int i = tid; i < CDIM * 16; i += 512) {
                int k = i >> 4, c8 = (i & 15) << 3;
                cp16(&s.w1s[k * W1LD + c8], &g_w1h[k * HID + hbn + c8]);
            }
            cp_commit();
        }

        // gemm2: acc += hb @ w2s
        for (int kk = 0; kk < 128; kk += 16) {
            wmma::fragment<wmma::matrix_a, 16, 16, 16, __half, wmma::row_major> af;
            wmma::load_matrix_sync(af, &s.hb[(rt * 16) * HBLD + kk], HBLD);
            #pragma unroll
            for (int c = 0; c < 6; c++) {
                wmma::fragment<wmma::matrix_b, 16, 16, 16, __half, wmma::row_major> bf;
                wmma::load_matrix_sync(bf, &s.w2s[kk * W2LD + cg * 96 + c * 16], W2LD);
                wmma::mma_sync(acc[c], af, bf, acc[c]);
            }
        }
        cp_wait0();
        __syncthreads();   // w1s[it+1] ready; safe to overwrite hb/w2s next iter
    }

    // epilogue
    #pragma unroll
    for (int c = 0; c < 6; c++) {
        wmma::store_matrix_sync(&s.stage[warp * 16 * SGLD], acc[c], SGLD, wmma::mem_row_major);
        __syncwarp();
        #pragma unroll
        for (int q = 0; q < 8; q++) {
            int idx = q * 32 + lane;
            int rr = idx >> 4, cc = idx & 15;
            int col = cg * 96 + c * 16 + cc;
            long long gi = (row0 + rt * 16 + rr) * CDIM + col;
            out[gi] = s.stage[warp * 16 * SGLD + rr * SGLD + cc] + s.b2[col] + g_data2[gi];
        }
        __syncwarp();
    }
}

// ---------------- launch ----------------
extern "C" void kernel_launch(void* const* d_in, const int* in_sizes, int n_in,
                              void* d_out, int out_size) {
    const float* data      = (const float*)d_in[0];
    const float* mask      = (const float*)d_in[1];
    const int*   rel_pos   = (const int*)  d_in[2];
    const float* ln1_g     = (const float*)d_in[3];
    const float* ln1_b     = (const float*)d_in[4];
    const float* qkv_w     = (const float*)d_in[5];
    const float* qkv_b     = (const float*)d_in[6];
    const float* rpe_table = (const float*)d_in[7];
    const float* proj_w    = (const float*)d_in[8];
    const float* proj_b    = (const float*)d_in[9];
    const float* ln2_g     = (const float*)d_in[10];
    const float* ln2_b     = (const float*)d_in[11];
    const float* mlp_w1    = (const float*)d_in[12];
    const float* mlp_b1    = (const float*)d_in[13];
    const float* mlp_w2    = (const float*)d_in[14];
    const float* mlp_b2    = (const float*)d_in[15];
    float* out = (float*)d_out;

    cudaFuncSetAttribute(kernelA, cudaFuncAttributeMaxDynamicSharedMemorySize, (int)sizeof(SmemA));
    cudaFuncSetAttribute(kernelB, cudaFuncAttributeMaxDynamicSharedMemorySize, (int)sizeof(SmemB));

    convert_weights<<<576, 256>>>(qkv_w, proj_w, mlp_w1, mlp_w2);
    kernelA<<<NWIN, 256, sizeof(SmemA)>>>(data, mask, rel_pos, ln1_g, ln1_b,
                                          qkv_b, rpe_table, proj_b);
    kernelB<<<(NWIN * KW) / 128, 512, sizeof(SmemB)>>>(ln2_g, ln2_b, mlp_b1, mlp_b2, out);
}